// round 1
// baseline (speedup 1.0000x reference)
#include <cuda_runtime.h>
#include <cuda_bf16.h>
#include <math.h>

// ---------------- problem constants ----------------
#define LSEQ 512
#define BB   8
#define EE   1024
#define HH   16
#define HD   64
#define NLAY 2
#define DFF  4096
#define MROWS (LSEQ*BB)          // 4096
#define BHN  (BB*HH)             // 128

// ---------------- scratch (device globals, float4 for 16B alignment) ----------------
__device__ float4 g_pt4  [(size_t)LSEQ*LSEQ*HD/4];     // pos+typ  [L,L,HD]
__device__ float4 g_qkv4 [(size_t)MROWS*3*EE/4];       // [L*B, 3E]
__device__ float4 g_Q4   [(size_t)BHN*LSEQ*HD/4];      // [bh, l, d]
__device__ float4 g_K4   [(size_t)BHN*LSEQ*HD/4];
__device__ float4 g_V4   [(size_t)BHN*LSEQ*HD/4];
__device__ float4 g_S4   [(size_t)BHN*LSEQ*LSEQ/4];    // [bh, l, s]
__device__ float4 g_AO4  [(size_t)BHN*LSEQ*HD/4];      // attn out [bh,l,d]
__device__ float4 g_AL4  [(size_t)MROWS*EE/4];         // attn out [l,b,e]
__device__ float4 g_Y4   [(size_t)MROWS*EE/4];
__device__ float4 g_X14  [(size_t)MROWS*EE/4];
__device__ float4 g_X4   [(size_t)MROWS*EE/4];
__device__ float4 g_H4   [(size_t)MROWS*DFF/4];        // ffn hidden

__device__ __forceinline__ float gelu_exact(float x) {
    return 0.5f * x * (1.0f + erff(x * 0.70710678118654752f));
}

// ---------------- generic NT/NN fp32 GEMM, 8x8 per thread ----------------
// C[M,N] (+)= A[M,K] * op(B) (+ bias[n], optional GELU)
// TRANSB=true : B is [N,K] row-major (NT);  false: B is [K,N] row-major (NN)
// EPI: 0=none, 1=+bias, 2=+bias then exact GELU.  ACCUM: C += result.
template<int BM, int BN, bool TRANSB, int EPI, bool ACCUM>
__global__ void sgemm(const float* __restrict__ A, int lda, long long sAz,
                      const float* __restrict__ B, int ldb, long long sBz,
                      float* __restrict__ C, int ldc, long long sCz,
                      const float* __restrict__ bias,
                      int M, int N, int K)
{
    constexpr int BK = 16;
    constexpr int THREADS = (BM/8)*(BN/8);
    __shared__ float As[BK][BM];
    __shared__ float Bs[BK][BN];

    A += (long long)blockIdx.z * sAz;
    B += (long long)blockIdx.z * sBz;
    C += (long long)blockIdx.z * sCz;

    const int bm = blockIdx.y * BM;
    const int bn = blockIdx.x * BN;
    const int tid = threadIdx.x;
    const int ty = tid / (BN/8);
    const int tx = tid % (BN/8);

    float acc[8][8];
    #pragma unroll
    for (int i = 0; i < 8; i++)
        #pragma unroll
        for (int j = 0; j < 8; j++) acc[i][j] = 0.f;

    for (int k0 = 0; k0 < K; k0 += BK) {
        // load A tile (always [row, k] -> transpose into As[k][row])
        for (int i = tid; i < BM*BK/4; i += THREADS) {
            int idx = i * 4;
            int row = idx / BK;
            int kk  = idx % BK;
            float4 v = *(const float4*)(A + (size_t)(bm + row) * lda + k0 + kk);
            As[kk+0][row] = v.x; As[kk+1][row] = v.y;
            As[kk+2][row] = v.z; As[kk+3][row] = v.w;
        }
        if (TRANSB) {
            for (int i = tid; i < BN*BK/4; i += THREADS) {
                int idx = i * 4;
                int row = idx / BK;
                int kk  = idx % BK;
                float4 v = *(const float4*)(B + (size_t)(bn + row) * ldb + k0 + kk);
                Bs[kk+0][row] = v.x; Bs[kk+1][row] = v.y;
                Bs[kk+2][row] = v.z; Bs[kk+3][row] = v.w;
            }
        } else {
            for (int i = tid; i < BN*BK/4; i += THREADS) {
                int idx = i * 4;
                int kk  = idx / BN;
                int col = idx % BN;
                *(float4*)&Bs[kk][col] =
                    *(const float4*)(B + (size_t)(k0 + kk) * ldb + bn + col);
            }
        }
        __syncthreads();

        #pragma unroll
        for (int kk = 0; kk < BK; kk++) {
            float a[8], b[8];
            *(float4*)&a[0] = *(const float4*)&As[kk][ty*8];
            *(float4*)&a[4] = *(const float4*)&As[kk][ty*8+4];
            *(float4*)&b[0] = *(const float4*)&Bs[kk][tx*8];
            *(float4*)&b[4] = *(const float4*)&Bs[kk][tx*8+4];
            #pragma unroll
            for (int i = 0; i < 8; i++)
                #pragma unroll
                for (int j = 0; j < 8; j++)
                    acc[i][j] += a[i] * b[j];
        }
        __syncthreads();
    }

    float bv[8];
    if (EPI >= 1) {
        #pragma unroll
        for (int j = 0; j < 8; j++) bv[j] = bias[bn + tx*8 + j];
    }
    #pragma unroll
    for (int i = 0; i < 8; i++) {
        float* Cp = C + (size_t)(bm + ty*8 + i) * ldc + bn + tx*8;
        #pragma unroll
        for (int jj = 0; jj < 8; jj += 4) {
            float4 v;
            v.x = acc[i][jj+0]; v.y = acc[i][jj+1];
            v.z = acc[i][jj+2]; v.w = acc[i][jj+3];
            if (EPI >= 1) { v.x += bv[jj+0]; v.y += bv[jj+1]; v.z += bv[jj+2]; v.w += bv[jj+3]; }
            if (EPI == 2) { v.x = gelu_exact(v.x); v.y = gelu_exact(v.y);
                            v.z = gelu_exact(v.z); v.w = gelu_exact(v.w); }
            if (ACCUM) {
                float4 o = *(float4*)(Cp + jj);
                v.x += o.x; v.y += o.y; v.z += o.z; v.w += o.w;
            }
            *(float4*)(Cp + jj) = v;
        }
    }
}

// ---------------- elementwise add (pt = pos + typ) ----------------
__global__ void add2_kernel(const float4* __restrict__ a, const float4* __restrict__ b,
                            float4* __restrict__ o, int n4)
{
    int i = blockIdx.x * blockDim.x + threadIdx.x;
    if (i < n4) {
        float4 x = a[i], y = b[i];
        o[i] = make_float4(x.x+y.x, x.y+y.y, x.z+y.z, x.w+y.w);
    }
}

// ---------------- split qkv [l,b,3E] -> Q(scaled)/K/V [bh,l,d] ----------------
__global__ void split_qkv_kernel(const float* __restrict__ qkv,
                                 float* __restrict__ Q, float* __restrict__ K,
                                 float* __restrict__ V)
{
    int t = blockIdx.x * blockDim.x + threadIdx.x;   // total 128*512*16
    int d4 = t & 15;
    int l  = (t >> 4) & 511;
    int bh = t >> 13;                                 // 0..127
    int b = bh >> 4, h = bh & 15;
    size_t src = (size_t)(l * BB + b) * (3*EE) + h * HD + d4 * 4;
    size_t dst = (size_t)bh * (LSEQ*HD) + l * HD + d4 * 4;
    float4 q = *(const float4*)(qkv + src);
    float4 k = *(const float4*)(qkv + src + EE);
    float4 v = *(const float4*)(qkv + src + 2*EE);
    const float s = 0.125f;   // HD^-0.5
    q.x *= s; q.y *= s; q.z *= s; q.w *= s;
    *(float4*)(Q + dst) = q;
    *(float4*)(K + dst) = k;
    *(float4*)(V + dst) = v;
}

// ---------------- reorder attn out [bh,l,d] -> [l,b,e] ----------------
__global__ void reorder_kernel(const float* __restrict__ AO, float* __restrict__ O)
{
    int t = blockIdx.x * blockDim.x + threadIdx.x;
    int d4 = t & 15;
    int l  = (t >> 4) & 511;
    int bh = t >> 13;
    int b = bh >> 4, h = bh & 15;
    size_t src = (size_t)bh * (LSEQ*HD) + l * HD + d4 * 4;
    size_t dst = (size_t)(l * BB + b) * EE + h * HD + d4 * 4;
    *(float4*)(O + dst) = *(const float4*)(AO + src);
}

// ---------------- softmax over rows of 512 (warp per row) ----------------
__global__ void softmax512_kernel(float* __restrict__ S)
{
    long long row = (long long)blockIdx.x * 8 + threadIdx.y;
    float* p = S + row * LSEQ;
    int lane = threadIdx.x;
    float v[16];
    float mx = -1e30f;
    #pragma unroll
    for (int i = 0; i < 16; i++) { v[i] = p[i*32 + lane]; mx = fmaxf(mx, v[i]); }
    #pragma unroll
    for (int o = 16; o; o >>= 1) mx = fmaxf(mx, __shfl_xor_sync(0xffffffffu, mx, o));
    float s = 0.f;
    #pragma unroll
    for (int i = 0; i < 16; i++) { v[i] = __expf(v[i] - mx); s += v[i]; }
    #pragma unroll
    for (int o = 16; o; o >>= 1) s += __shfl_xor_sync(0xffffffffu, s, o);
    float inv = 1.0f / s;
    #pragma unroll
    for (int i = 0; i < 16; i++) p[i*32 + lane] = v[i] * inv;
}

// ---------------- LN(residual) over rows of 1024 ----------------
__global__ void ln_res_kernel(const float* __restrict__ X, const float* __restrict__ Y,
                              const float* __restrict__ g, const float* __restrict__ be,
                              float* __restrict__ O)
{
    int row = blockIdx.x;
    int t = threadIdx.x;      // 256 threads, 1 float4 each
    const float4* x4 = (const float4*)(X + (size_t)row * EE);
    const float4* y4 = (const float4*)(Y + (size_t)row * EE);
    float4 a = x4[t], b = y4[t];
    float4 v = make_float4(a.x+b.x, a.y+b.y, a.z+b.z, a.w+b.w);
    float s = v.x + v.y + v.z + v.w;
    float q = v.x*v.x + v.y*v.y + v.z*v.z + v.w*v.w;
    __shared__ float sh_s[8], sh_q[8];
    #pragma unroll
    for (int o = 16; o; o >>= 1) {
        s += __shfl_xor_sync(0xffffffffu, s, o);
        q += __shfl_xor_sync(0xffffffffu, q, o);
    }
    int wid = t >> 5, lane = t & 31;
    if (!lane) { sh_s[wid] = s; sh_q[wid] = q; }
    __syncthreads();
    if (t < 32) {
        s = (lane < 8) ? sh_s[lane] : 0.f;
        q = (lane < 8) ? sh_q[lane] : 0.f;
        #pragma unroll
        for (int o = 4; o; o >>= 1) {
            s += __shfl_xor_sync(0xffffffffu, s, o);
            q += __shfl_xor_sync(0xffffffffu, q, o);
        }
        if (!lane) { sh_s[0] = s; sh_q[0] = q; }
    }
    __syncthreads();
    float mean = sh_s[0] * (1.f/EE);
    float var  = sh_q[0] * (1.f/EE) - mean * mean;
    float r = rsqrtf(var + 1e-5f);
    float4 gg = ((const float4*)g)[t];
    float4 bb = ((const float4*)be)[t];
    float4 o;
    o.x = (v.x - mean) * r * gg.x + bb.x;
    o.y = (v.y - mean) * r * gg.y + bb.y;
    o.z = (v.z - mean) * r * gg.z + bb.z;
    o.w = (v.w - mean) * r * gg.w + bb.w;
    ((float4*)(O + (size_t)row * EE))[t] = o;
}

// ---------------- launch ----------------
static float* sym(const void* devSymbol) {
    void* p = nullptr;
    cudaGetSymbolAddress(&p, devSymbol);
    return (float*)p;
}

extern "C" void kernel_launch(void* const* d_in, const int* in_sizes, int n_in,
                              void* d_out, int out_size)
{
    const float* src = (const float*)d_in[0];
    const float* pos = (const float*)d_in[1];
    const float* typ = (const float*)d_in[2];
    const float* Wi  = (const float*)d_in[3];
    const float* bi  = (const float*)d_in[4];
    const float* Wo  = (const float*)d_in[5];
    const float* bo  = (const float*)d_in[6];
    const float* W1  = (const float*)d_in[7];
    const float* b1  = (const float*)d_in[8];
    const float* W2  = (const float*)d_in[9];
    const float* b2  = (const float*)d_in[10];
    const float* g1  = (const float*)d_in[11];
    const float* be1 = (const float*)d_in[12];
    const float* g2  = (const float*)d_in[13];
    const float* be2 = (const float*)d_in[14];
    float* out = (float*)d_out;

    float* PT  = sym(g_pt4);
    float* QKV = sym(g_qkv4);
    float* Q   = sym(g_Q4);
    float* K   = sym(g_K4);
    float* V   = sym(g_V4);
    float* S   = sym(g_S4);
    float* AO  = sym(g_AO4);
    float* AL  = sym(g_AL4);
    float* Y   = sym(g_Y4);
    float* X1  = sym(g_X14);
    float* X   = sym(g_X4);
    float* Hb  = sym(g_H4);

    // pt = pos + typ : 512*512*64 = 16,777,216 floats = 4,194,304 float4
    add2_kernel<<<16384, 256>>>((const float4*)pos, (const float4*)typ,
                                (float4*)PT, 4194304);

    const float* x = src;
    for (int l = 0; l < NLAY; l++) {
        // 1) QKV = x @ Wi^T + bi      [4096,3072] K=1024
        sgemm<128,128,true,1,false><<<dim3(24,32,1), 256>>>(
            x, EE, 0, Wi + (size_t)l*3*EE*EE, EE, 0,
            QKV, 3*EE, 0, bi + (size_t)l*3*EE, MROWS, 3*EE, EE);

        // 2) split + scale Q
        split_qkv_kernel<<<4096, 256>>>(QKV, Q, K, V);

        // 3) scores = Q @ K^T  (batched over bh=128)  [512,512] K=64
        sgemm<128,128,true,0,false><<<dim3(4,4,BHN), 256>>>(
            Q, HD, (long long)LSEQ*HD, K, HD, (long long)LSEQ*HD,
            S, LSEQ, (long long)LSEQ*LSEQ, nullptr, LSEQ, LSEQ, HD);

        // 4) scores[:,l,:] += Qf[l] @ pt[l]^T (batched over l=512) [128,512] K=64
        sgemm<128,128,true,0,true><<<dim3(4,1,LSEQ), 256>>>(
            Q, LSEQ*HD, (long long)HD,
            PT, HD, (long long)LSEQ*HD,
            S, LSEQ*LSEQ, (long long)LSEQ,
            nullptr, BHN, LSEQ, HD);

        // 5) softmax rows (128*512 rows of 512)
        softmax512_kernel<<<BHN*LSEQ/8, dim3(32,8)>>>(S);

        // 6) AO = W @ V (batched over bh)  [512,64] K=512, NN
        sgemm<128,64,false,0,false><<<dim3(1,4,BHN), 128>>>(
            S, LSEQ, (long long)LSEQ*LSEQ, V, HD, (long long)LSEQ*HD,
            AO, HD, (long long)LSEQ*HD, nullptr, LSEQ, HD, LSEQ);

        // 7) AO[:,l,:] += W_l @ pt[l] (batched over l) [128,64] K=512, NN
        sgemm<128,64,false,0,true><<<dim3(1,1,LSEQ), 128>>>(
            S, LSEQ*LSEQ, (long long)LSEQ,
            PT, HD, (long long)LSEQ*HD,
            AO, LSEQ*HD, (long long)HD,
            nullptr, BHN, HD, LSEQ);

        // 8) reorder [bh,l,d] -> [l,b,e]
        reorder_kernel<<<4096, 256>>>(AO, AL);

        // 9) Y = AL @ Wo^T + bo   [4096,1024] K=1024
        sgemm<128,128,true,1,false><<<dim3(8,32,1), 256>>>(
            AL, EE, 0, Wo + (size_t)l*EE*EE, EE, 0,
            Y, EE, 0, bo + (size_t)l*EE, MROWS, EE, EE);

        // 10) X1 = LN(x + Y)
        ln_res_kernel<<<MROWS, 256>>>(x, Y, g1 + (size_t)l*EE, be1 + (size_t)l*EE, X1);

        // 11) H = gelu(X1 @ W1^T + b1)   [4096,4096] K=1024
        sgemm<128,128,true,2,false><<<dim3(32,32,1), 256>>>(
            X1, EE, 0, W1 + (size_t)l*DFF*EE, EE, 0,
            Hb, DFF, 0, b1 + (size_t)l*DFF, MROWS, DFF, EE);

        // 12) Y = H @ W2^T + b2   [4096,1024] K=4096
        sgemm<128,128,true,1,false><<<dim3(8,32,1), 256>>>(
            Hb, DFF, 0, W2 + (size_t)l*EE*DFF, DFF, 0,
            Y, EE, 0, b2 + (size_t)l*EE, MROWS, EE, DFF);

        // 13) next = LN(X1 + Y)   (last layer writes d_out)
        float* xo = (l == NLAY-1) ? out : X;
        ln_res_kernel<<<MROWS, 256>>>(X1, Y, g2 + (size_t)l*EE, be2 + (size_t)l*EE, xo);

        x = X;
    }
}

// round 2
// speedup vs baseline: 3.0137x; 3.0137x over previous
#include <cuda_runtime.h>
#include <cuda_bf16.h>
#include <math.h>
#include <stdint.h>

// ---------------- problem constants ----------------
#define LSEQ 512
#define BB   8
#define EE   1024
#define HH   16
#define HD   64
#define NLAY 2
#define DFF  4096
#define MROWS (LSEQ*BB)          // 4096
#define BHN  (BB*HH)             // 128

// ---------------- scratch (device globals) ----------------
__device__ float4 g_pt4  [(size_t)LSEQ*LSEQ*HD/4];     // pos+typ  [L,L,HD]
__device__ float4 g_qkv4 [(size_t)MROWS*3*EE/4];       // [L*B, 3E]
__device__ float4 g_Q4   [(size_t)BHN*LSEQ*HD/4];      // [bh, l, d]
__device__ float4 g_K4   [(size_t)BHN*LSEQ*HD/4];
__device__ float4 g_V4   [(size_t)BHN*LSEQ*HD/4];
__device__ float4 g_S4   [(size_t)BHN*LSEQ*LSEQ/4];    // [bh, l, s]
__device__ float4 g_AO4  [(size_t)BHN*LSEQ*HD/4];      // attn out [bh,l,d]
__device__ float4 g_AL4  [(size_t)MROWS*EE/4];         // attn out [l,b,e]
__device__ float4 g_Y4   [(size_t)MROWS*EE/4];
__device__ float4 g_X14  [(size_t)MROWS*EE/4];
__device__ float4 g_X4   [(size_t)MROWS*EE/4];
__device__ float4 g_H4   [(size_t)MROWS*DFF/4];        // ffn hidden

__device__ __forceinline__ float gelu_exact(float x) {
    return 0.5f * x * (1.0f + erff(x * 0.70710678118654752f));
}

__device__ __forceinline__ uint32_t f2tf(float x) {
    uint32_t u;
    asm("cvt.rna.tf32.f32 %0, %1;" : "=r"(u) : "f"(x));
    return u;
}

// ---------------- TF32 tensor-core GEMM ----------------
// C[M,N] (+)= A[M,K] * op(B)  (+ bias[n], optional exact GELU)
// TRANSB=true : B is [N,K] row-major (NT);  false: B is [K,N] row-major (NN)
// EPI: 0=none, 1=+bias, 2=+bias then GELU.  ACCUM: C += result.
// Block: BM x BN, warp tile WM x WN, mma m16n8k8.
template<int BM, int BN, int WM, int WN, bool TRANSB, int EPI, bool ACCUM>
__global__ void __launch_bounds__((BM/WM)*(BN/WN)*32)
tgemm(const float* __restrict__ A, int lda, long long sAz,
      const float* __restrict__ B, int ldb, long long sBz,
      float* __restrict__ C, int ldc, long long sCz,
      const float* __restrict__ bias,
      int M, int N, int K)
{
    constexpr int BK = 32;
    constexpr int WARPS_M = BM / WM;
    constexpr int WARPS_N = BN / WN;
    constexpr int THREADS = WARPS_M * WARPS_N * 32;
    constexpr int LDSA = BK + 4;    // 36 -> fragment reads conflict-free (banks 4g+c)
    constexpr int MI = WM / 16;
    constexpr int NI = WN / 8;

    __shared__ uint32_t As[BM][LDSA];
    __shared__ uint32_t Bs[BN][LDSA];

    A += (long long)blockIdx.z * sAz;
    B += (long long)blockIdx.z * sBz;
    C += (long long)blockIdx.z * sCz;

    const int bm = blockIdx.y * BM;
    const int bn = blockIdx.x * BN;
    const int tid  = threadIdx.x;
    const int wid  = tid >> 5;
    const int lane = tid & 31;
    const int wm = (wid / WARPS_N) * WM;
    const int wn = (wid % WARPS_N) * WN;
    const int g = lane >> 2;   // group id (row within 16x8 tile)
    const int c = lane & 3;    // thread-in-group

    float acc[MI][NI][4];
    #pragma unroll
    for (int mi = 0; mi < MI; mi++)
        #pragma unroll
        for (int ni = 0; ni < NI; ni++)
            #pragma unroll
            for (int r = 0; r < 4; r++) acc[mi][ni][r] = 0.f;

    for (int k0 = 0; k0 < K; k0 += BK) {
        // --- load A tile: [BM rows][BK k], coalesced float4 row copies ---
        #pragma unroll
        for (int i = tid; i < BM * (BK/4); i += THREADS) {
            int row = i >> 3;
            int kk  = (i & 7) * 4;
            float4 v = *(const float4*)(A + (size_t)(bm + row) * lda + k0 + kk);
            As[row][kk+0] = f2tf(v.x); As[row][kk+1] = f2tf(v.y);
            As[row][kk+2] = f2tf(v.z); As[row][kk+3] = f2tf(v.w);
        }
        // --- load B tile into Bs[n][k] ---
        if (TRANSB) {
            #pragma unroll
            for (int i = tid; i < BN * (BK/4); i += THREADS) {
                int row = i >> 3;
                int kk  = (i & 7) * 4;
                float4 v = *(const float4*)(B + (size_t)(bn + row) * ldb + k0 + kk);
                Bs[row][kk+0] = f2tf(v.x); Bs[row][kk+1] = f2tf(v.y);
                Bs[row][kk+2] = f2tf(v.z); Bs[row][kk+3] = f2tf(v.w);
            }
        } else {
            #pragma unroll
            for (int i = tid; i < BK * (BN/4); i += THREADS) {
                int kk  = i / (BN/4);
                int col = (i % (BN/4)) * 4;
                float4 v = *(const float4*)(B + (size_t)(k0 + kk) * ldb + bn + col);
                Bs[col+0][kk] = f2tf(v.x); Bs[col+1][kk] = f2tf(v.y);
                Bs[col+2][kk] = f2tf(v.z); Bs[col+3][kk] = f2tf(v.w);
            }
        }
        __syncthreads();

        #pragma unroll
        for (int kk = 0; kk < BK; kk += 8) {
            uint32_t af[MI][4], bf[NI][2];
            #pragma unroll
            for (int mi = 0; mi < MI; mi++) {
                const uint32_t* p0 = &As[wm + mi*16 + g][kk + c];
                const uint32_t* p1 = &As[wm + mi*16 + g + 8][kk + c];
                af[mi][0] = p0[0]; af[mi][2] = p0[4];
                af[mi][1] = p1[0]; af[mi][3] = p1[4];
            }
            #pragma unroll
            for (int ni = 0; ni < NI; ni++) {
                const uint32_t* p = &Bs[wn + ni*8 + g][kk + c];
                bf[ni][0] = p[0]; bf[ni][1] = p[4];
            }
            #pragma unroll
            for (int mi = 0; mi < MI; mi++)
                #pragma unroll
                for (int ni = 0; ni < NI; ni++) {
                    asm volatile(
                        "mma.sync.aligned.m16n8k8.row.col.f32.tf32.tf32.f32 "
                        "{%0,%1,%2,%3}, {%4,%5,%6,%7}, {%8,%9}, {%0,%1,%2,%3};\n"
                        : "+f"(acc[mi][ni][0]), "+f"(acc[mi][ni][1]),
                          "+f"(acc[mi][ni][2]), "+f"(acc[mi][ni][3])
                        : "r"(af[mi][0]), "r"(af[mi][1]),
                          "r"(af[mi][2]), "r"(af[mi][3]),
                          "r"(bf[ni][0]), "r"(bf[ni][1]));
                }
        }
        __syncthreads();
    }

    // ---- epilogue ----
    #pragma unroll
    for (int mi = 0; mi < MI; mi++) {
        #pragma unroll
        for (int ni = 0; ni < NI; ni++) {
            int row = bm + wm + mi*16 + g;
            int col = bn + wn + ni*8 + 2*c;
            float bx = 0.f, by = 0.f;
            if (EPI >= 1) { bx = bias[col]; by = bias[col+1]; }
            #pragma unroll
            for (int half = 0; half < 2; half++) {
                int r = row + half*8;
                float vx = acc[mi][ni][half*2+0];
                float vy = acc[mi][ni][half*2+1];
                if (EPI >= 1) { vx += bx; vy += by; }
                if (EPI == 2) { vx = gelu_exact(vx); vy = gelu_exact(vy); }
                float2* Cp = (float2*)(C + (size_t)r * ldc + col);
                if (ACCUM) {
                    float2 o = *Cp;
                    vx += o.x; vy += o.y;
                }
                *Cp = make_float2(vx, vy);
            }
        }
    }
}

// ---------------- elementwise add (pt = pos + typ) ----------------
__global__ void add2_kernel(const float4* __restrict__ a, const float4* __restrict__ b,
                            float4* __restrict__ o, int n4)
{
    int i = blockIdx.x * blockDim.x + threadIdx.x;
    if (i < n4) {
        float4 x = a[i], y = b[i];
        o[i] = make_float4(x.x+y.x, x.y+y.y, x.z+y.z, x.w+y.w);
    }
}

// ---------------- split qkv [l,b,3E] -> Q(scaled)/K/V [bh,l,d] ----------------
__global__ void split_qkv_kernel(const float* __restrict__ qkv,
                                 float* __restrict__ Q, float* __restrict__ K,
                                 float* __restrict__ V)
{
    int t = blockIdx.x * blockDim.x + threadIdx.x;
    int d4 = t & 15;
    int l  = (t >> 4) & 511;
    int bh = t >> 13;
    int b = bh >> 4, h = bh & 15;
    size_t src = (size_t)(l * BB + b) * (3*EE) + h * HD + d4 * 4;
    size_t dst = (size_t)bh * (LSEQ*HD) + l * HD + d4 * 4;
    float4 q = *(const float4*)(qkv + src);
    float4 k = *(const float4*)(qkv + src + EE);
    float4 v = *(const float4*)(qkv + src + 2*EE);
    const float s = 0.125f;   // HD^-0.5
    q.x *= s; q.y *= s; q.z *= s; q.w *= s;
    *(float4*)(Q + dst) = q;
    *(float4*)(K + dst) = k;
    *(float4*)(V + dst) = v;
}

// ---------------- reorder attn out [bh,l,d] -> [l,b,e] ----------------
__global__ void reorder_kernel(const float* __restrict__ AO, float* __restrict__ O)
{
    int t = blockIdx.x * blockDim.x + threadIdx.x;
    int d4 = t & 15;
    int l  = (t >> 4) & 511;
    int bh = t >> 13;
    int b = bh >> 4, h = bh & 15;
    size_t src = (size_t)bh * (LSEQ*HD) + l * HD + d4 * 4;
    size_t dst = (size_t)(l * BB + b) * EE + h * HD + d4 * 4;
    *(float4*)(O + dst) = *(const float4*)(AO + src);
}

// ---------------- softmax over rows of 512 (warp per row) ----------------
__global__ void softmax512_kernel(float* __restrict__ S)
{
    long long row = (long long)blockIdx.x * 8 + threadIdx.y;
    float* p = S + row * LSEQ;
    int lane = threadIdx.x;
    float v[16];
    float mx = -1e30f;
    #pragma unroll
    for (int i = 0; i < 16; i++) { v[i] = p[i*32 + lane]; mx = fmaxf(mx, v[i]); }
    #pragma unroll
    for (int o = 16; o; o >>= 1) mx = fmaxf(mx, __shfl_xor_sync(0xffffffffu, mx, o));
    float s = 0.f;
    #pragma unroll
    for (int i = 0; i < 16; i++) { v[i] = __expf(v[i] - mx); s += v[i]; }
    #pragma unroll
    for (int o = 16; o; o >>= 1) s += __shfl_xor_sync(0xffffffffu, s, o);
    float inv = 1.0f / s;
    #pragma unroll
    for (int i = 0; i < 16; i++) p[i*32 + lane] = v[i] * inv;
}

// ---------------- LN(residual) over rows of 1024 ----------------
__global__ void ln_res_kernel(const float* __restrict__ X, const float* __restrict__ Y,
                              const float* __restrict__ g, const float* __restrict__ be,
                              float* __restrict__ O)
{
    int row = blockIdx.x;
    int t = threadIdx.x;      // 256 threads, 1 float4 each
    const float4* x4 = (const float4*)(X + (size_t)row * EE);
    const float4* y4 = (const float4*)(Y + (size_t)row * EE);
    float4 a = x4[t], b = y4[t];
    float4 v = make_float4(a.x+b.x, a.y+b.y, a.z+b.z, a.w+b.w);
    float s = v.x + v.y + v.z + v.w;
    float q = v.x*v.x + v.y*v.y + v.z*v.z + v.w*v.w;
    __shared__ float sh_s[8], sh_q[8];
    #pragma unroll
    for (int o = 16; o; o >>= 1) {
        s += __shfl_xor_sync(0xffffffffu, s, o);
        q += __shfl_xor_sync(0xffffffffu, q, o);
    }
    int wid = t >> 5, lane = t & 31;
    if (!lane) { sh_s[wid] = s; sh_q[wid] = q; }
    __syncthreads();
    if (t < 32) {
        s = (lane < 8) ? sh_s[lane] : 0.f;
        q = (lane < 8) ? sh_q[lane] : 0.f;
        #pragma unroll
        for (int o = 4; o; o >>= 1) {
            s += __shfl_xor_sync(0xffffffffu, s, o);
            q += __shfl_xor_sync(0xffffffffu, q, o);
        }
        if (!lane) { sh_s[0] = s; sh_q[0] = q; }
    }
    __syncthreads();
    float mean = sh_s[0] * (1.f/EE);
    float var  = sh_q[0] * (1.f/EE) - mean * mean;
    float r = rsqrtf(var + 1e-5f);
    float4 gg = ((const float4*)g)[t];
    float4 bb = ((const float4*)be)[t];
    float4 o;
    o.x = (v.x - mean) * r * gg.x + bb.x;
    o.y = (v.y - mean) * r * gg.y + bb.y;
    o.z = (v.z - mean) * r * gg.z + bb.z;
    o.w = (v.w - mean) * r * gg.w + bb.w;
    ((float4*)(O + (size_t)row * EE))[t] = o;
}

// ---------------- launch ----------------
static float* sym(const void* devSymbol) {
    void* p = nullptr;
    cudaGetSymbolAddress(&p, devSymbol);
    return (float*)p;
}

extern "C" void kernel_launch(void* const* d_in, const int* in_sizes, int n_in,
                              void* d_out, int out_size)
{
    const float* src = (const float*)d_in[0];
    const float* pos = (const float*)d_in[1];
    const float* typ = (const float*)d_in[2];
    const float* Wi  = (const float*)d_in[3];
    const float* bi  = (const float*)d_in[4];
    const float* Wo  = (const float*)d_in[5];
    const float* bo  = (const float*)d_in[6];
    const float* W1  = (const float*)d_in[7];
    const float* b1  = (const float*)d_in[8];
    const float* W2  = (const float*)d_in[9];
    const float* b2  = (const float*)d_in[10];
    const float* g1  = (const float*)d_in[11];
    const float* be1 = (const float*)d_in[12];
    const float* g2  = (const float*)d_in[13];
    const float* be2 = (const float*)d_in[14];
    float* out = (float*)d_out;

    float* PT  = sym(g_pt4);
    float* QKV = sym(g_qkv4);
    float* Q   = sym(g_Q4);
    float* K   = sym(g_K4);
    float* V   = sym(g_V4);
    float* S   = sym(g_S4);
    float* AO  = sym(g_AO4);
    float* AL  = sym(g_AL4);
    float* Y   = sym(g_Y4);
    float* X1  = sym(g_X14);
    float* X   = sym(g_X4);
    float* Hb  = sym(g_H4);

    // pt = pos + typ
    add2_kernel<<<16384, 256>>>((const float4*)pos, (const float4*)typ,
                                (float4*)PT, 4194304);

    const float* x = src;
    for (int l = 0; l < NLAY; l++) {
        // 1) QKV = x @ Wi^T + bi      [4096,3072] K=1024
        tgemm<128,128,64,64,true,1,false><<<dim3(24,32,1), 128>>>(
            x, EE, 0, Wi + (size_t)l*3*EE*EE, EE, 0,
            QKV, 3*EE, 0, bi + (size_t)l*3*EE, MROWS, 3*EE, EE);

        // 2) split + scale Q
        split_qkv_kernel<<<4096, 256>>>(QKV, Q, K, V);

        // 3) scores = Q @ K^T  (batched over bh=128)  [512,512] K=64
        tgemm<128,128,64,64,true,0,false><<<dim3(4,4,BHN), 128>>>(
            Q, HD, (long long)LSEQ*HD, K, HD, (long long)LSEQ*HD,
            S, LSEQ, (long long)LSEQ*LSEQ, nullptr, LSEQ, LSEQ, HD);

        // 4) scores[:,l,:] += Qf[l] @ pt[l]^T (batched over l=512) [128,512] K=64
        tgemm<128,128,64,64,true,0,true><<<dim3(4,1,LSEQ), 128>>>(
            Q, LSEQ*HD, (long long)HD,
            PT, HD, (long long)LSEQ*HD,
            S, LSEQ*LSEQ, (long long)LSEQ,
            nullptr, BHN, LSEQ, HD);

        // 5) softmax rows (128*512 rows of 512)
        softmax512_kernel<<<BHN*LSEQ/8, dim3(32,8)>>>(S);

        // 6) AO = W @ V (batched over bh)  [512,64] K=512, NN
        tgemm<128,64,64,32,false,0,false><<<dim3(1,4,BHN), 128>>>(
            S, LSEQ, (long long)LSEQ*LSEQ, V, HD, (long long)LSEQ*HD,
            AO, HD, (long long)LSEQ*HD, nullptr, LSEQ, HD, LSEQ);

        // 7) AO[:,l,:] += W_l @ pt[l] (batched over l) [128,64] K=512, NN
        tgemm<128,64,64,32,false,0,true><<<dim3(1,1,LSEQ), 128>>>(
            S, LSEQ*LSEQ, (long long)LSEQ,
            PT, HD, (long long)LSEQ*HD,
            AO, LSEQ*HD, (long long)HD,
            nullptr, BHN, HD, LSEQ);

        // 8) reorder [bh,l,d] -> [l,b,e]
        reorder_kernel<<<4096, 256>>>(AO, AL);

        // 9) Y = AL @ Wo^T + bo   [4096,1024] K=1024
        tgemm<128,128,64,64,true,1,false><<<dim3(8,32,1), 128>>>(
            AL, EE, 0, Wo + (size_t)l*EE*EE, EE, 0,
            Y, EE, 0, bo + (size_t)l*EE, MROWS, EE, EE);

        // 10) X1 = LN(x + Y)
        ln_res_kernel<<<MROWS, 256>>>(x, Y, g1 + (size_t)l*EE, be1 + (size_t)l*EE, X1);

        // 11) H = gelu(X1 @ W1^T + b1)   [4096,4096] K=1024
        tgemm<128,128,64,64,true,2,false><<<dim3(32,32,1), 128>>>(
            X1, EE, 0, W1 + (size_t)l*DFF*EE, EE, 0,
            Hb, DFF, 0, b1 + (size_t)l*DFF, MROWS, DFF, EE);

        // 12) Y = H @ W2^T + b2   [4096,1024] K=4096
        tgemm<128,128,64,64,true,1,false><<<dim3(8,32,1), 128>>>(
            Hb, DFF, 0, W2 + (size_t)l*EE*DFF, DFF, 0,
            Y, EE, 0, b2 + (size_t)l*EE, MROWS, EE, DFF);

        // 13) next = LN(X1 + Y)   (last layer writes d_out)
        float* xo = (l == NLAY-1) ? out : X;
        ln_res_kernel<<<MROWS, 256>>>(X1, Y, g2 + (size_t)l*EE, be2 + (size_t)l*EE, xo);

        x = X;
    }
}

// round 3
// speedup vs baseline: 3.3972x; 1.1272x over previous
#include <cuda_runtime.h>
#include <cuda_bf16.h>
#include <math.h>
#include <stdint.h>

// ---------------- problem constants ----------------
#define LSEQ 512
#define BB   8
#define EE   1024
#define HH   16
#define HD   64
#define NLAY 2
#define DFF  4096
#define MROWS (LSEQ*BB)          // 4096
#define BHN  (BB*HH)             // 128

// ---------------- scratch (device globals) ----------------
__device__ float4 g_pt4  [(size_t)LSEQ*LSEQ*HD/4];     // pos+typ  [L,L,HD]
__device__ float4 g_qkv4 [(size_t)MROWS*3*EE/4];       // [L*B, 3E]
__device__ float4 g_Q4   [(size_t)BHN*LSEQ*HD/4];      // [bh, l, d]
__device__ float4 g_K4   [(size_t)BHN*LSEQ*HD/4];
__device__ float4 g_V4   [(size_t)BHN*LSEQ*HD/4];
__device__ float4 g_S4   [(size_t)BHN*LSEQ*LSEQ/4];    // [bh, l, s]
__device__ float4 g_AO4  [(size_t)BHN*LSEQ*HD/4];      // attn out [bh,l,d]
__device__ float4 g_AL4  [(size_t)MROWS*EE/4];         // attn out [l,b,e]
__device__ float4 g_Y4   [(size_t)MROWS*EE/4];
__device__ float4 g_X14  [(size_t)MROWS*EE/4];
__device__ float4 g_X4   [(size_t)MROWS*EE/4];
__device__ float4 g_H4   [(size_t)MROWS*DFF/4];        // ffn hidden

__device__ __forceinline__ float gelu_exact(float x) {
    return 0.5f * x * (1.0f + erff(x * 0.70710678118654752f));
}

__device__ __forceinline__ void cp16(uint32_t saddr, const void* gaddr) {
    asm volatile("cp.async.cg.shared.global [%0], [%1], 16;\n"
                 :: "r"(saddr), "l"(gaddr));
}
__device__ __forceinline__ void cp_commit() {
    asm volatile("cp.async.commit_group;\n");
}
template<int N>
__device__ __forceinline__ void cp_wait() {
    asm volatile("cp.async.wait_group %0;\n" :: "n"(N));
}

// ---------------- TF32 tensor-core GEMM, cp.async 2-stage pipeline ----------------
// C[M,N] (+)= A[M,K] * op(B)  (+ bias[n], optional exact GELU)
// TRANSB=true : B is [N,K] row-major (NT);  false: B is [K,N] row-major (NN)
// EPI: 0=none, 1=+bias, 2=+bias then GELU.  ACCUM: C += result.
template<int BM, int BN, int WM, int WN, bool TRANSB, int EPI, bool ACCUM>
__global__ void __launch_bounds__((BM/WM)*(BN/WN)*32, 2)
tgemm(const float* __restrict__ A, int lda, long long sAz,
      const float* __restrict__ B, int ldb, long long sBz,
      float* __restrict__ C, int ldc, long long sCz,
      const float* __restrict__ bias,
      int M, int N, int K)
{
    constexpr int BK = 32;
    constexpr int WARPS_M = BM / WM;
    constexpr int WARPS_N = BN / WN;
    constexpr int THREADS = WARPS_M * WARPS_N * 32;
    constexpr int LDSA = BK + 4;                       // 36
    constexpr int LDSB = TRANSB ? (BK + 4) : (BN + 4);
    constexpr int A_WORDS = BM * LDSA;
    constexpr int B_WORDS = TRANSB ? (BN * LDSA) : (BK * LDSB);
    constexpr int STAGE_WORDS = A_WORDS + B_WORDS;
    constexpr int MI = WM / 16;
    constexpr int NI = WN / 8;

    extern __shared__ uint32_t smem[];

    A += (long long)blockIdx.z * sAz;
    B += (long long)blockIdx.z * sBz;
    C += (long long)blockIdx.z * sCz;

    const int bm = blockIdx.y * BM;
    const int bn = blockIdx.x * BN;
    const int tid  = threadIdx.x;
    const int wid  = tid >> 5;
    const int lane = tid & 31;
    const int wm = (wid / WARPS_N) * WM;
    const int wn = (wid % WARPS_N) * WN;
    const int g = lane >> 2;   // row group within mma tile
    const int c = lane & 3;    // thread-in-group

    // smem byte base addresses for cp.async
    uint32_t smem_base;
    asm("{ .reg .u64 t; cvta.to.shared.u64 t, %1; cvt.u32.u64 %0, t; }"
        : "=r"(smem_base) : "l"(smem));

    float acc[MI][NI][4];
    #pragma unroll
    for (int mi = 0; mi < MI; mi++)
        #pragma unroll
        for (int ni = 0; ni < NI; ni++)
            #pragma unroll
            for (int r = 0; r < 4; r++) acc[mi][ni][r] = 0.f;

    const int nIter = K / BK;

    // ---- tile load (cp.async) ----
    auto load_tiles = [&](int stage, int k0) {
        uint32_t sA = smem_base + (uint32_t)(stage * STAGE_WORDS) * 4u;
        uint32_t sB = sA + (uint32_t)A_WORDS * 4u;
        #pragma unroll
        for (int i = tid; i < BM * (BK/4); i += THREADS) {
            int row = i / (BK/4);
            int kc  = (i % (BK/4)) * 4;
            cp16(sA + (uint32_t)(row * LDSA + kc) * 4u,
                 A + (size_t)(bm + row) * lda + k0 + kc);
        }
        if (TRANSB) {
            #pragma unroll
            for (int i = tid; i < BN * (BK/4); i += THREADS) {
                int row = i / (BK/4);
                int kc  = (i % (BK/4)) * 4;
                cp16(sB + (uint32_t)(row * LDSA + kc) * 4u,
                     B + (size_t)(bn + row) * ldb + k0 + kc);
            }
        } else {
            #pragma unroll
            for (int i = tid; i < BK * (BN/4); i += THREADS) {
                int kk  = i / (BN/4);
                int col = (i % (BN/4)) * 4;
                cp16(sB + (uint32_t)(kk * LDSB + col) * 4u,
                     B + (size_t)(k0 + kk) * ldb + bn + col);
            }
        }
        cp_commit();
    };

    load_tiles(0, 0);

    for (int it = 0; it < nIter; it++) {
        const int cur = it & 1;
        if (it + 1 < nIter) {
            load_tiles(cur ^ 1, (it + 1) * BK);
            cp_wait<1>();
        } else {
            cp_wait<0>();
        }
        __syncthreads();

        const uint32_t* As = smem + cur * STAGE_WORDS;
        const uint32_t* Bs = As + A_WORDS;

        #pragma unroll
        for (int kk = 0; kk < BK; kk += 8) {
            uint32_t af[MI][4], bf[NI][2];
            #pragma unroll
            for (int mi = 0; mi < MI; mi++) {
                const uint32_t* p0 = &As[(wm + mi*16 + g) * LDSA + kk + c];
                const uint32_t* p1 = &As[(wm + mi*16 + g + 8) * LDSA + kk + c];
                af[mi][0] = p0[0]; af[mi][2] = p0[4];
                af[mi][1] = p1[0]; af[mi][3] = p1[4];
            }
            #pragma unroll
            for (int ni = 0; ni < NI; ni++) {
                if (TRANSB) {
                    const uint32_t* p = &Bs[(wn + ni*8 + g) * LDSA + kk + c];
                    bf[ni][0] = p[0]; bf[ni][1] = p[4];
                } else {
                    bf[ni][0] = Bs[(kk + c)     * LDSB + wn + ni*8 + g];
                    bf[ni][1] = Bs[(kk + c + 4) * LDSB + wn + ni*8 + g];
                }
            }
            #pragma unroll
            for (int mi = 0; mi < MI; mi++)
                #pragma unroll
                for (int ni = 0; ni < NI; ni++) {
                    asm volatile(
                        "mma.sync.aligned.m16n8k8.row.col.f32.tf32.tf32.f32 "
                        "{%0,%1,%2,%3}, {%4,%5,%6,%7}, {%8,%9}, {%0,%1,%2,%3};\n"
                        : "+f"(acc[mi][ni][0]), "+f"(acc[mi][ni][1]),
                          "+f"(acc[mi][ni][2]), "+f"(acc[mi][ni][3])
                        : "r"(af[mi][0]), "r"(af[mi][1]),
                          "r"(af[mi][2]), "r"(af[mi][3]),
                          "r"(bf[ni][0]), "r"(bf[ni][1]));
                }
        }
        __syncthreads();
    }

    // ---- epilogue ----
    #pragma unroll
    for (int mi = 0; mi < MI; mi++) {
        #pragma unroll
        for (int ni = 0; ni < NI; ni++) {
            int row = bm + wm + mi*16 + g;
            int col = bn + wn + ni*8 + 2*c;
            float bx = 0.f, by = 0.f;
            if (EPI >= 1) { bx = bias[col]; by = bias[col+1]; }
            #pragma unroll
            for (int half = 0; half < 2; half++) {
                int r = row + half*8;
                float vx = acc[mi][ni][half*2+0];
                float vy = acc[mi][ni][half*2+1];
                if (EPI >= 1) { vx += bx; vy += by; }
                if (EPI == 2) { vx = gelu_exact(vx); vy = gelu_exact(vy); }
                float2* Cp = (float2*)(C + (size_t)r * ldc + col);
                if (ACCUM) {
                    float2 o = *Cp;
                    vx += o.x; vy += o.y;
                }
                *Cp = make_float2(vx, vy);
            }
        }
    }
}

// ---------------- elementwise add (pt = pos + typ) ----------------
__global__ void add2_kernel(const float4* __restrict__ a, const float4* __restrict__ b,
                            float4* __restrict__ o, int n4)
{
    int i = blockIdx.x * blockDim.x + threadIdx.x;
    if (i < n4) {
        float4 x = a[i], y = b[i];
        o[i] = make_float4(x.x+y.x, x.y+y.y, x.z+y.z, x.w+y.w);
    }
}

// ---------------- split qkv [l,b,3E] -> Q(scaled)/K/V [bh,l,d] ----------------
__global__ void split_qkv_kernel(const float* __restrict__ qkv,
                                 float* __restrict__ Q, float* __restrict__ K,
                                 float* __restrict__ V)
{
    int t = blockIdx.x * blockDim.x + threadIdx.x;
    int d4 = t & 15;
    int l  = (t >> 4) & 511;
    int bh = t >> 13;
    int b = bh >> 4, h = bh & 15;
    size_t src = (size_t)(l * BB + b) * (3*EE) + h * HD + d4 * 4;
    size_t dst = (size_t)bh * (LSEQ*HD) + l * HD + d4 * 4;
    float4 q = *(const float4*)(qkv + src);
    float4 k = *(const float4*)(qkv + src + EE);
    float4 v = *(const float4*)(qkv + src + 2*EE);
    const float s = 0.125f;   // HD^-0.5
    q.x *= s; q.y *= s; q.z *= s; q.w *= s;
    *(float4*)(Q + dst) = q;
    *(float4*)(K + dst) = k;
    *(float4*)(V + dst) = v;
}

// ---------------- reorder attn out [bh,l,d] -> [l,b,e] ----------------
__global__ void reorder_kernel(const float* __restrict__ AO, float* __restrict__ O)
{
    int t = blockIdx.x * blockDim.x + threadIdx.x;
    int d4 = t & 15;
    int l  = (t >> 4) & 511;
    int bh = t >> 13;
    int b = bh >> 4, h = bh & 15;
    size_t src = (size_t)bh * (LSEQ*HD) + l * HD + d4 * 4;
    size_t dst = (size_t)(l * BB + b) * EE + h * HD + d4 * 4;
    *(float4*)(O + dst) = *(const float4*)(AO + src);
}

// ---------------- softmax over rows of 512 (warp per row) ----------------
__global__ void softmax512_kernel(float* __restrict__ S)
{
    long long row = (long long)blockIdx.x * 8 + threadIdx.y;
    float* p = S + row * LSEQ;
    int lane = threadIdx.x;
    float v[16];
    float mx = -1e30f;
    #pragma unroll
    for (int i = 0; i < 16; i++) { v[i] = p[i*32 + lane]; mx = fmaxf(mx, v[i]); }
    #pragma unroll
    for (int o = 16; o; o >>= 1) mx = fmaxf(mx, __shfl_xor_sync(0xffffffffu, mx, o));
    float s = 0.f;
    #pragma unroll
    for (int i = 0; i < 16; i++) { v[i] = __expf(v[i] - mx); s += v[i]; }
    #pragma unroll
    for (int o = 16; o; o >>= 1) s += __shfl_xor_sync(0xffffffffu, s, o);
    float inv = 1.0f / s;
    #pragma unroll
    for (int i = 0; i < 16; i++) p[i*32 + lane] = v[i] * inv;
}

// ---------------- LN(residual) over rows of 1024 ----------------
__global__ void ln_res_kernel(const float* __restrict__ X, const float* __restrict__ Y,
                              const float* __restrict__ g, const float* __restrict__ be,
                              float* __restrict__ O)
{
    int row = blockIdx.x;
    int t = threadIdx.x;      // 256 threads, 1 float4 each
    const float4* x4 = (const float4*)(X + (size_t)row * EE);
    const float4* y4 = (const float4*)(Y + (size_t)row * EE);
    float4 a = x4[t], b = y4[t];
    float4 v = make_float4(a.x+b.x, a.y+b.y, a.z+b.z, a.w+b.w);
    float s = v.x + v.y + v.z + v.w;
    float q = v.x*v.x + v.y*v.y + v.z*v.z + v.w*v.w;
    __shared__ float sh_s[8], sh_q[8];
    #pragma unroll
    for (int o = 16; o; o >>= 1) {
        s += __shfl_xor_sync(0xffffffffu, s, o);
        q += __shfl_xor_sync(0xffffffffu, q, o);
    }
    int wid = t >> 5, lane = t & 31;
    if (!lane) { sh_s[wid] = s; sh_q[wid] = q; }
    __syncthreads();
    if (t < 32) {
        s = (lane < 8) ? sh_s[lane] : 0.f;
        q = (lane < 8) ? sh_q[lane] : 0.f;
        #pragma unroll
        for (int o = 4; o; o >>= 1) {
            s += __shfl_xor_sync(0xffffffffu, s, o);
            q += __shfl_xor_sync(0xffffffffu, q, o);
        }
        if (!lane) { sh_s[0] = s; sh_q[0] = q; }
    }
    __syncthreads();
    float mean = sh_s[0] * (1.f/EE);
    float var  = sh_q[0] * (1.f/EE) - mean * mean;
    float r = rsqrtf(var + 1e-5f);
    float4 gg = ((const float4*)g)[t];
    float4 bb = ((const float4*)be)[t];
    float4 o;
    o.x = (v.x - mean) * r * gg.x + bb.x;
    o.y = (v.y - mean) * r * gg.y + bb.y;
    o.z = (v.z - mean) * r * gg.z + bb.z;
    o.w = (v.w - mean) * r * gg.w + bb.w;
    ((float4*)(O + (size_t)row * EE))[t] = o;
}

// ---------------- launch ----------------
static float* sym(const void* devSymbol) {
    void* p = nullptr;
    cudaGetSymbolAddress(&p, devSymbol);
    return (float*)p;
}

// smem sizes (bytes): 2 stages * (A words + B words) * 4
#define SMEM_NT_128x128 (2 * (128*36 + 128*36) * 4)   // 73728
#define SMEM_NN_128x64  (2 * (128*36 + 32*68) * 4)    // 54272

extern "C" void kernel_launch(void* const* d_in, const int* in_sizes, int n_in,
                              void* d_out, int out_size)
{
    const float* src = (const float*)d_in[0];
    const float* pos = (const float*)d_in[1];
    const float* typ = (const float*)d_in[2];
    const float* Wi  = (const float*)d_in[3];
    const float* bi  = (const float*)d_in[4];
    const float* Wo  = (const float*)d_in[5];
    const float* bo  = (const float*)d_in[6];
    const float* W1  = (const float*)d_in[7];
    const float* b1  = (const float*)d_in[8];
    const float* W2  = (const float*)d_in[9];
    const float* b2  = (const float*)d_in[10];
    const float* g1  = (const float*)d_in[11];
    const float* be1 = (const float*)d_in[12];
    const float* g2  = (const float*)d_in[13];
    const float* be2 = (const float*)d_in[14];
    float* out = (float*)d_out;

    float* PT  = sym(g_pt4);
    float* QKV = sym(g_qkv4);
    float* Q   = sym(g_Q4);
    float* K   = sym(g_K4);
    float* V   = sym(g_V4);
    float* S   = sym(g_S4);
    float* AO  = sym(g_AO4);
    float* AL  = sym(g_AL4);
    float* Y   = sym(g_Y4);
    float* X1  = sym(g_X14);
    float* X   = sym(g_X4);
    float* Hb  = sym(g_H4);

    // raise dynamic smem limits (host-side attribute set; not stream work)
    static bool attrs_done = false;
    if (!attrs_done) {
        cudaFuncSetAttribute(tgemm<128,128,64,32,true,1,false>,
                             cudaFuncAttributeMaxDynamicSharedMemorySize, SMEM_NT_128x128);
        cudaFuncSetAttribute(tgemm<128,128,64,32,true,0,false>,
                             cudaFuncAttributeMaxDynamicSharedMemorySize, SMEM_NT_128x128);
        cudaFuncSetAttribute(tgemm<128,128,64,32,true,0,true>,
                             cudaFuncAttributeMaxDynamicSharedMemorySize, SMEM_NT_128x128);
        cudaFuncSetAttribute(tgemm<128,128,64,32,true,2,false>,
                             cudaFuncAttributeMaxDynamicSharedMemorySize, SMEM_NT_128x128);
        cudaFuncSetAttribute(tgemm<128,64,64,32,false,0,false>,
                             cudaFuncAttributeMaxDynamicSharedMemorySize, SMEM_NN_128x64);
        cudaFuncSetAttribute(tgemm<128,64,64,32,false,0,true>,
                             cudaFuncAttributeMaxDynamicSharedMemorySize, SMEM_NN_128x64);
        attrs_done = true;
    }

    // pt = pos + typ
    add2_kernel<<<16384, 256>>>((const float4*)pos, (const float4*)typ,
                                (float4*)PT, 4194304);

    const float* x = src;
    for (int l = 0; l < NLAY; l++) {
        // 1) QKV = x @ Wi^T + bi      [4096,3072] K=1024
        tgemm<128,128,64,32,true,1,false><<<dim3(24,32,1), 256, SMEM_NT_128x128>>>(
            x, EE, 0, Wi + (size_t)l*3*EE*EE, EE, 0,
            QKV, 3*EE, 0, bi + (size_t)l*3*EE, MROWS, 3*EE, EE);

        // 2) split + scale Q
        split_qkv_kernel<<<4096, 256>>>(QKV, Q, K, V);

        // 3) scores = Q @ K^T  (batched over bh=128)  [512,512] K=64
        tgemm<128,128,64,32,true,0,false><<<dim3(4,4,BHN), 256, SMEM_NT_128x128>>>(
            Q, HD, (long long)LSEQ*HD, K, HD, (long long)LSEQ*HD,
            S, LSEQ, (long long)LSEQ*LSEQ, nullptr, LSEQ, LSEQ, HD);

        // 4) scores[:,l,:] += Qf[l] @ pt[l]^T (batched over l=512) [128,512] K=64
        tgemm<128,128,64,32,true,0,true><<<dim3(4,1,LSEQ), 256, SMEM_NT_128x128>>>(
            Q, LSEQ*HD, (long long)HD,
            PT, HD, (long long)LSEQ*HD,
            S, LSEQ*LSEQ, (long long)LSEQ,
            nullptr, BHN, LSEQ, HD);

        // 5) softmax rows (128*512 rows of 512)
        softmax512_kernel<<<BHN*LSEQ/8, dim3(32,8)>>>(S);

        // 6) AO = W @ V (batched over bh)  [512,64] K=512, NN
        tgemm<128,64,64,32,false,0,false><<<dim3(1,4,BHN), 128, SMEM_NN_128x64>>>(
            S, LSEQ, (long long)LSEQ*LSEQ, V, HD, (long long)LSEQ*HD,
            AO, HD, (long long)LSEQ*HD, nullptr, LSEQ, HD, LSEQ);

        // 7) AO[:,l,:] += W_l @ pt[l] (batched over l) [128,64] K=512, NN
        tgemm<128,64,64,32,false,0,true><<<dim3(1,1,LSEQ), 128, SMEM_NN_128x64>>>(
            S, LSEQ*LSEQ, (long long)LSEQ,
            PT, HD, (long long)LSEQ*HD,
            AO, LSEQ*HD, (long long)HD,
            nullptr, BHN, HD, LSEQ);

        // 8) reorder [bh,l,d] -> [l,b,e]
        reorder_kernel<<<4096, 256>>>(AO, AL);

        // 9) Y = AL @ Wo^T + bo   [4096,1024] K=1024
        tgemm<128,128,64,32,true,1,false><<<dim3(8,32,1), 256, SMEM_NT_128x128>>>(
            AL, EE, 0, Wo + (size_t)l*EE*EE, EE, 0,
            Y, EE, 0, bo + (size_t)l*EE, MROWS, EE, EE);

        // 10) X1 = LN(x + Y)
        ln_res_kernel<<<MROWS, 256>>>(x, Y, g1 + (size_t)l*EE, be1 + (size_t)l*EE, X1);

        // 11) H = gelu(X1 @ W1^T + b1)   [4096,4096] K=1024
        tgemm<128,128,64,32,true,2,false><<<dim3(32,32,1), 256, SMEM_NT_128x128>>>(
            X1, EE, 0, W1 + (size_t)l*DFF*EE, EE, 0,
            Hb, DFF, 0, b1 + (size_t)l*DFF, MROWS, DFF, EE);

        // 12) Y = H @ W2^T + b2   [4096,1024] K=4096
        tgemm<128,128,64,32,true,1,false><<<dim3(8,32,1), 256, SMEM_NT_128x128>>>(
            Hb, DFF, 0, W2 + (size_t)l*EE*DFF, DFF, 0,
            Y, EE, 0, b2 + (size_t)l*EE, MROWS, EE, DFF);

        // 13) next = LN(X1 + Y)   (last layer writes d_out)
        float* xo = (l == NLAY-1) ? out : X;
        ln_res_kernel<<<MROWS, 256>>>(X1, Y, g2 + (size_t)l*EE, be2 + (size_t)l*EE, xo);

        x = X;
    }
}

// round 4
// speedup vs baseline: 3.4104x; 1.0039x over previous
#include <cuda_runtime.h>
#include <cuda_bf16.h>
#include <math.h>
#include <stdint.h>

// ---------------- problem constants ----------------
#define LSEQ 512
#define BB   8
#define EE   1024
#define HH   16
#define HD   64
#define NLAY 2
#define DFF  4096
#define MROWS (LSEQ*BB)          // 4096
#define BHN  (BB*HH)             // 128

// ---------------- scratch (device globals) ----------------
__device__ float4 g_pt4  [(size_t)LSEQ*LSEQ*HD/4];     // pos+typ (rounded) [L,L,HD]
__device__ float4 g_qkv4 [(size_t)MROWS*3*EE/4];       // [L*B, 3E]
__device__ float4 g_Q4   [(size_t)BHN*LSEQ*HD/4];      // [bh, l, d] rounded
__device__ float4 g_K4   [(size_t)BHN*LSEQ*HD/4];
__device__ float4 g_V4   [(size_t)BHN*LSEQ*HD/4];
__device__ float4 g_S4   [(size_t)BHN*LSEQ*LSEQ/4];    // [bh, l, s]
__device__ float4 g_AO4  [(size_t)BHN*LSEQ*HD/4];      // attn out [bh,l,d]
__device__ float4 g_AL4  [(size_t)MROWS*EE/4];         // attn out [l,b,e] rounded
__device__ float4 g_Y4   [(size_t)MROWS*EE/4];
__device__ float4 g_X14  [(size_t)MROWS*EE/4];         // exact LN1 out
__device__ float4 g_X1r4 [(size_t)MROWS*EE/4];         // rounded LN1 out
__device__ float4 g_X4   [(size_t)MROWS*EE/4];         // exact layer out
__device__ float4 g_Xr4  [(size_t)MROWS*EE/4];         // rounded layer out / src
__device__ float4 g_H4   [(size_t)MROWS*DFF/4];        // ffn hidden (rounded)
// rounded weights
__device__ float4 g_Wir4 [(size_t)NLAY*3*EE*EE/4];
__device__ float4 g_Wor4 [(size_t)NLAY*EE*EE/4];
__device__ float4 g_W1r4 [(size_t)NLAY*DFF*EE/4];
__device__ float4 g_W2r4 [(size_t)NLAY*EE*DFF/4];

__device__ __forceinline__ float gelu_exact(float x) {
    return 0.5f * x * (1.0f + erff(x * 0.70710678118654752f));
}

__device__ __forceinline__ uint32_t f2tf(float x) {
    uint32_t u;
    asm("cvt.rna.tf32.f32 %0, %1;" : "=r"(u) : "f"(x));
    return u;
}
__device__ __forceinline__ float rndtf(float x) { return __uint_as_float(f2tf(x)); }

__device__ __forceinline__ void cp16(uint32_t saddr, const void* gaddr) {
    asm volatile("cp.async.cg.shared.global [%0], [%1], 16;\n"
                 :: "r"(saddr), "l"(gaddr));
}
__device__ __forceinline__ void cp_commit() {
    asm volatile("cp.async.commit_group;\n");
}
template<int N>
__device__ __forceinline__ void cp_wait() {
    asm volatile("cp.async.wait_group %0;\n" :: "n"(N));
}

// ---------------- TF32 tensor-core GEMM, cp.async 3-stage pipeline ----------------
// Inputs are assumed pre-rounded to TF32 (RNA) in gmem.
// C[M,N] (+)= A[M,K] * op(B)  (+ bias[n], optional exact GELU, optional tf32-round)
template<int BM, int BN, int WM, int WN, bool TRANSB, int EPI, bool ACCUM, bool ROUND>
__global__ void __launch_bounds__((BM/WM)*(BN/WN)*32, 2)
tgemm(const float* __restrict__ A, int lda, long long sAz,
      const float* __restrict__ B, int ldb, long long sBz,
      float* __restrict__ C, int ldc, long long sCz,
      const float* __restrict__ bias,
      int M, int N, int K)
{
    constexpr int BK = 32;
    constexpr int WARPS_M = BM / WM;
    constexpr int WARPS_N = BN / WN;
    constexpr int THREADS = WARPS_M * WARPS_N * 32;
    constexpr int LDSA = BK + 4;                       // 36
    constexpr int LDSB = TRANSB ? (BK + 4) : (BN + 8);
    constexpr int A_WORDS = BM * LDSA;
    constexpr int B_WORDS = TRANSB ? (BN * LDSA) : (BK * LDSB);
    constexpr int STAGE_WORDS = A_WORDS + B_WORDS;
    constexpr int NSTAGE = 3;
    constexpr int MI = WM / 16;
    constexpr int NI = WN / 8;

    extern __shared__ uint32_t smem[];

    A += (long long)blockIdx.z * sAz;
    B += (long long)blockIdx.z * sBz;
    C += (long long)blockIdx.z * sCz;

    const int bm = blockIdx.y * BM;
    const int bn = blockIdx.x * BN;
    const int tid  = threadIdx.x;
    const int wid  = tid >> 5;
    const int lane = tid & 31;
    const int wm = (wid / WARPS_N) * WM;
    const int wn = (wid % WARPS_N) * WN;
    const int g = lane >> 2;
    const int c = lane & 3;

    uint32_t smem_base;
    asm("{ .reg .u64 t; cvta.to.shared.u64 t, %1; cvt.u32.u64 %0, t; }"
        : "=r"(smem_base) : "l"(smem));

    float acc[MI][NI][4];
    #pragma unroll
    for (int mi = 0; mi < MI; mi++)
        #pragma unroll
        for (int ni = 0; ni < NI; ni++)
            #pragma unroll
            for (int r = 0; r < 4; r++) acc[mi][ni][r] = 0.f;

    const int nIter = K / BK;

    auto load_tiles = [&](int stage, int k0) {
        uint32_t sA = smem_base + (uint32_t)(stage * STAGE_WORDS) * 4u;
        uint32_t sB = sA + (uint32_t)A_WORDS * 4u;
        #pragma unroll
        for (int i = tid; i < BM * (BK/4); i += THREADS) {
            int row = i / (BK/4);
            int kc  = (i % (BK/4)) * 4;
            cp16(sA + (uint32_t)(row * LDSA + kc) * 4u,
                 A + (size_t)(bm + row) * lda + k0 + kc);
        }
        if (TRANSB) {
            #pragma unroll
            for (int i = tid; i < BN * (BK/4); i += THREADS) {
                int row = i / (BK/4);
                int kc  = (i % (BK/4)) * 4;
                cp16(sB + (uint32_t)(row * LDSA + kc) * 4u,
                     B + (size_t)(bn + row) * ldb + k0 + kc);
            }
        } else {
            #pragma unroll
            for (int i = tid; i < BK * (BN/4); i += THREADS) {
                int kk  = i / (BN/4);
                int col = (i % (BN/4)) * 4;
                cp16(sB + (uint32_t)(kk * LDSB + col) * 4u,
                     B + (size_t)(k0 + kk) * ldb + bn + col);
            }
        }
        cp_commit();
    };

    load_tiles(0, 0);
    load_tiles(1, BK);   // nIter >= 2 always in this network

    for (int it = 0; it < nIter; it++) {
        __syncthreads();   // all warps done reading the buffer we're about to overwrite
        if (it + 2 < nIter) {
            load_tiles((it + 2) % NSTAGE, (it + 2) * BK);
            cp_wait<2>();
        } else if (it + 1 < nIter) {
            cp_wait<1>();
        } else {
            cp_wait<0>();
        }
        __syncthreads();

        const uint32_t* As = smem + (it % NSTAGE) * STAGE_WORDS;
        const uint32_t* Bs = As + A_WORDS;

        #pragma unroll
        for (int kk = 0; kk < BK; kk += 8) {
            uint32_t af[MI][4], bf[NI][2];
            #pragma unroll
            for (int mi = 0; mi < MI; mi++) {
                const uint32_t* p0 = &As[(wm + mi*16 + g) * LDSA + kk + c];
                const uint32_t* p1 = &As[(wm + mi*16 + g + 8) * LDSA + kk + c];
                af[mi][0] = p0[0]; af[mi][2] = p0[4];
                af[mi][1] = p1[0]; af[mi][3] = p1[4];
            }
            #pragma unroll
            for (int ni = 0; ni < NI; ni++) {
                if (TRANSB) {
                    const uint32_t* p = &Bs[(wn + ni*8 + g) * LDSA + kk + c];
                    bf[ni][0] = p[0]; bf[ni][1] = p[4];
                } else {
                    bf[ni][0] = Bs[(kk + c)     * LDSB + wn + ni*8 + g];
                    bf[ni][1] = Bs[(kk + c + 4) * LDSB + wn + ni*8 + g];
                }
            }
            #pragma unroll
            for (int mi = 0; mi < MI; mi++)
                #pragma unroll
                for (int ni = 0; ni < NI; ni++) {
                    asm volatile(
                        "mma.sync.aligned.m16n8k8.row.col.f32.tf32.tf32.f32 "
                        "{%0,%1,%2,%3}, {%4,%5,%6,%7}, {%8,%9}, {%0,%1,%2,%3};\n"
                        : "+f"(acc[mi][ni][0]), "+f"(acc[mi][ni][1]),
                          "+f"(acc[mi][ni][2]), "+f"(acc[mi][ni][3])
                        : "r"(af[mi][0]), "r"(af[mi][1]),
                          "r"(af[mi][2]), "r"(af[mi][3]),
                          "r"(bf[ni][0]), "r"(bf[ni][1]));
                }
        }
    }

    // ---- epilogue ----
    #pragma unroll
    for (int mi = 0; mi < MI; mi++) {
        #pragma unroll
        for (int ni = 0; ni < NI; ni++) {
            int row = bm + wm + mi*16 + g;
            int col = bn + wn + ni*8 + 2*c;
            float bx = 0.f, by = 0.f;
            if (EPI >= 1) { bx = bias[col]; by = bias[col+1]; }
            #pragma unroll
            for (int half = 0; half < 2; half++) {
                int r = row + half*8;
                float vx = acc[mi][ni][half*2+0];
                float vy = acc[mi][ni][half*2+1];
                if (EPI >= 1) { vx += bx; vy += by; }
                if (EPI == 2) { vx = gelu_exact(vx); vy = gelu_exact(vy); }
                if (ROUND)    { vx = rndtf(vx); vy = rndtf(vy); }
                float2* Cp = (float2*)(C + (size_t)r * ldc + col);
                if (ACCUM) {
                    float2 o = *Cp;
                    vx += o.x; vy += o.y;
                }
                *Cp = make_float2(vx, vy);
            }
        }
    }
}

// ---------------- elementwise rounded add (pt = round(pos + typ)) ----------------
__global__ void add2r_kernel(const float4* __restrict__ a, const float4* __restrict__ b,
                             float4* __restrict__ o, int n4)
{
    int i = blockIdx.x * blockDim.x + threadIdx.x;
    if (i < n4) {
        float4 x = a[i], y = b[i];
        o[i] = make_float4(rndtf(x.x+y.x), rndtf(x.y+y.y),
                           rndtf(x.z+y.z), rndtf(x.w+y.w));
    }
}

// ---------------- elementwise tf32-round ----------------
__global__ void round4_kernel(const float4* __restrict__ a, float4* __restrict__ o, int n4)
{
    int i = blockIdx.x * blockDim.x + threadIdx.x;
    if (i < n4) {
        float4 x = a[i];
        o[i] = make_float4(rndtf(x.x), rndtf(x.y), rndtf(x.z), rndtf(x.w));
    }
}

// ---------------- split qkv [l,b,3E] -> Q(scaled)/K/V [bh,l,d], rounded ----------------
__global__ void split_qkv_kernel(const float* __restrict__ qkv,
                                 float* __restrict__ Q, float* __restrict__ K,
                                 float* __restrict__ V)
{
    int t = blockIdx.x * blockDim.x + threadIdx.x;
    int d4 = t & 15;
    int l  = (t >> 4) & 511;
    int bh = t >> 13;
    int b = bh >> 4, h = bh & 15;
    size_t src = (size_t)(l * BB + b) * (3*EE) + h * HD + d4 * 4;
    size_t dst = (size_t)bh * (LSEQ*HD) + l * HD + d4 * 4;
    float4 q = *(const float4*)(qkv + src);
    float4 k = *(const float4*)(qkv + src + EE);
    float4 v = *(const float4*)(qkv + src + 2*EE);
    const float s = 0.125f;   // HD^-0.5
    q = make_float4(rndtf(q.x*s), rndtf(q.y*s), rndtf(q.z*s), rndtf(q.w*s));
    k = make_float4(rndtf(k.x), rndtf(k.y), rndtf(k.z), rndtf(k.w));
    v = make_float4(rndtf(v.x), rndtf(v.y), rndtf(v.z), rndtf(v.w));
    *(float4*)(Q + dst) = q;
    *(float4*)(K + dst) = k;
    *(float4*)(V + dst) = v;
}

// ---------------- reorder attn out [bh,l,d] -> [l,b,e], rounded ----------------
__global__ void reorder_kernel(const float* __restrict__ AO, float* __restrict__ O)
{
    int t = blockIdx.x * blockDim.x + threadIdx.x;
    int d4 = t & 15;
    int l  = (t >> 4) & 511;
    int bh = t >> 13;
    int b = bh >> 4, h = bh & 15;
    size_t src = (size_t)bh * (LSEQ*HD) + l * HD + d4 * 4;
    size_t dst = (size_t)(l * BB + b) * EE + h * HD + d4 * 4;
    float4 v = *(const float4*)(AO + src);
    *(float4*)(O + dst) = make_float4(rndtf(v.x), rndtf(v.y), rndtf(v.z), rndtf(v.w));
}

// ---------------- softmax over rows of 512 (warp per row), rounded store ----------------
__global__ void softmax512_kernel(float* __restrict__ S)
{
    long long row = (long long)blockIdx.x * 8 + threadIdx.y;
    float* p = S + row * LSEQ;
    int lane = threadIdx.x;
    float v[16];
    float mx = -1e30f;
    #pragma unroll
    for (int i = 0; i < 16; i++) { v[i] = p[i*32 + lane]; mx = fmaxf(mx, v[i]); }
    #pragma unroll
    for (int o = 16; o; o >>= 1) mx = fmaxf(mx, __shfl_xor_sync(0xffffffffu, mx, o));
    float s = 0.f;
    #pragma unroll
    for (int i = 0; i < 16; i++) { v[i] = __expf(v[i] - mx); s += v[i]; }
    #pragma unroll
    for (int o = 16; o; o >>= 1) s += __shfl_xor_sync(0xffffffffu, s, o);
    float inv = 1.0f / s;
    #pragma unroll
    for (int i = 0; i < 16; i++) p[i*32 + lane] = rndtf(v[i] * inv);
}

// ---------------- LN(residual) over rows of 1024; exact out + optional rounded copy ----------------
__global__ void ln_res_kernel(const float* __restrict__ X, const float* __restrict__ Y,
                              const float* __restrict__ g, const float* __restrict__ be,
                              float* __restrict__ O, float* __restrict__ Or)
{
    int row = blockIdx.x;
    int t = threadIdx.x;      // 256 threads, 1 float4 each
    const float4* x4 = (const float4*)(X + (size_t)row * EE);
    const float4* y4 = (const float4*)(Y + (size_t)row * EE);
    float4 a = x4[t], b = y4[t];
    float4 v = make_float4(a.x+b.x, a.y+b.y, a.z+b.z, a.w+b.w);
    float s = v.x + v.y + v.z + v.w;
    float q = v.x*v.x + v.y*v.y + v.z*v.z + v.w*v.w;
    __shared__ float sh_s[8], sh_q[8];
    #pragma unroll
    for (int o = 16; o; o >>= 1) {
        s += __shfl_xor_sync(0xffffffffu, s, o);
        q += __shfl_xor_sync(0xffffffffu, q, o);
    }
    int wid = t >> 5, lane = t & 31;
    if (!lane) { sh_s[wid] = s; sh_q[wid] = q; }
    __syncthreads();
    if (t < 32) {
        s = (lane < 8) ? sh_s[lane] : 0.f;
        q = (lane < 8) ? sh_q[lane] : 0.f;
        #pragma unroll
        for (int o = 4; o; o >>= 1) {
            s += __shfl_xor_sync(0xffffffffu, s, o);
            q += __shfl_xor_sync(0xffffffffu, q, o);
        }
        if (!lane) { sh_s[0] = s; sh_q[0] = q; }
    }
    __syncthreads();
    float mean = sh_s[0] * (1.f/EE);
    float var  = sh_q[0] * (1.f/EE) - mean * mean;
    float r = rsqrtf(var + 1e-5f);
    float4 gg = ((const float4*)g)[t];
    float4 bb = ((const float4*)be)[t];
    float4 o;
    o.x = (v.x - mean) * r * gg.x + bb.x;
    o.y = (v.y - mean) * r * gg.y + bb.y;
    o.z = (v.z - mean) * r * gg.z + bb.z;
    o.w = (v.w - mean) * r * gg.w + bb.w;
    ((float4*)(O + (size_t)row * EE))[t] = o;
    if (Or) {
        float4 orr = make_float4(rndtf(o.x), rndtf(o.y), rndtf(o.z), rndtf(o.w));
        ((float4*)(Or + (size_t)row * EE))[t] = orr;
    }
}

// ---------------- launch ----------------
static float* sym(const void* devSymbol) {
    void* p = nullptr;
    cudaGetSymbolAddress(&p, devSymbol);
    return (float*)p;
}

// smem (bytes): 3 stages * stage_words * 4
#define SMEM_NT_128x128 (3 * (128*36 + 128*36) * 4)   // 110592
#define SMEM_NN_128x64  (3 * (128*36 + 32*72) * 4)    // 82944

extern "C" void kernel_launch(void* const* d_in, const int* in_sizes, int n_in,
                              void* d_out, int out_size)
{
    const float* src = (const float*)d_in[0];
    const float* pos = (const float*)d_in[1];
    const float* typ = (const float*)d_in[2];
    const float* Wi  = (const float*)d_in[3];
    const float* bi  = (const float*)d_in[4];
    const float* Wo  = (const float*)d_in[5];
    const float* bo  = (const float*)d_in[6];
    const float* W1  = (const float*)d_in[7];
    const float* b1  = (const float*)d_in[8];
    const float* W2  = (const float*)d_in[9];
    const float* b2  = (const float*)d_in[10];
    const float* g1  = (const float*)d_in[11];
    const float* be1 = (const float*)d_in[12];
    const float* g2  = (const float*)d_in[13];
    const float* be2 = (const float*)d_in[14];
    float* out = (float*)d_out;

    float* PT  = sym(g_pt4);
    float* QKV = sym(g_qkv4);
    float* Q   = sym(g_Q4);
    float* K   = sym(g_K4);
    float* V   = sym(g_V4);
    float* S   = sym(g_S4);
    float* AO  = sym(g_AO4);
    float* AL  = sym(g_AL4);
    float* Y   = sym(g_Y4);
    float* X1  = sym(g_X14);
    float* X1r = sym(g_X1r4);
    float* X   = sym(g_X4);
    float* Xr  = sym(g_Xr4);
    float* Hb  = sym(g_H4);
    float* Wir = sym(g_Wir4);
    float* Wor = sym(g_Wor4);
    float* W1r = sym(g_W1r4);
    float* W2r = sym(g_W2r4);

    static bool attrs_done = false;
    if (!attrs_done) {
        cudaFuncSetAttribute(tgemm<128,128,64,32,true,1,false,false>,
                             cudaFuncAttributeMaxDynamicSharedMemorySize, SMEM_NT_128x128);
        cudaFuncSetAttribute(tgemm<128,128,64,32,true,0,false,false>,
                             cudaFuncAttributeMaxDynamicSharedMemorySize, SMEM_NT_128x128);
        cudaFuncSetAttribute(tgemm<128,128,64,32,true,0,true,false>,
                             cudaFuncAttributeMaxDynamicSharedMemorySize, SMEM_NT_128x128);
        cudaFuncSetAttribute(tgemm<128,128,64,32,true,2,false,true>,
                             cudaFuncAttributeMaxDynamicSharedMemorySize, SMEM_NT_128x128);
        cudaFuncSetAttribute(tgemm<128,64,32,32,false,0,false,false>,
                             cudaFuncAttributeMaxDynamicSharedMemorySize, SMEM_NN_128x64);
        cudaFuncSetAttribute(tgemm<128,64,32,32,false,0,true,false>,
                             cudaFuncAttributeMaxDynamicSharedMemorySize, SMEM_NN_128x64);
        attrs_done = true;
    }

    // pre-round constant GEMM inputs (RNA tf32)
    add2r_kernel<<<16384, 256>>>((const float4*)pos, (const float4*)typ,
                                 (float4*)PT, 4194304);
    round4_kernel<<<(NLAY*3*EE*EE/4 + 255)/256, 256>>>((const float4*)Wi, (float4*)Wir, NLAY*3*EE*EE/4);
    round4_kernel<<<(NLAY*EE*EE/4   + 255)/256, 256>>>((const float4*)Wo, (float4*)Wor, NLAY*EE*EE/4);
    round4_kernel<<<(NLAY*DFF*EE/4  + 255)/256, 256>>>((const float4*)W1, (float4*)W1r, NLAY*DFF*EE/4);
    round4_kernel<<<(NLAY*EE*DFF/4  + 255)/256, 256>>>((const float4*)W2, (float4*)W2r, NLAY*EE*DFF/4);
    round4_kernel<<<(MROWS*EE/4     + 255)/256, 256>>>((const float4*)src, (float4*)Xr, MROWS*EE/4);

    const float* x = src;     // exact residual input
    for (int l = 0; l < NLAY; l++) {
        // 1) QKV = Xr @ Wir^T + bi      [4096,3072] K=1024
        tgemm<128,128,64,32,true,1,false,false><<<dim3(24,32,1), 256, SMEM_NT_128x128>>>(
            Xr, EE, 0, Wir + (size_t)l*3*EE*EE, EE, 0,
            QKV, 3*EE, 0, bi + (size_t)l*3*EE, MROWS, 3*EE, EE);

        // 2) split + scale Q (rounded)
        split_qkv_kernel<<<4096, 256>>>(QKV, Q, K, V);

        // 3) scores = Q @ K^T  (batched over bh=128)  [512,512] K=64
        tgemm<128,128,64,32,true,0,false,false><<<dim3(4,4,BHN), 256, SMEM_NT_128x128>>>(
            Q, HD, (long long)LSEQ*HD, K, HD, (long long)LSEQ*HD,
            S, LSEQ, (long long)LSEQ*LSEQ, nullptr, LSEQ, LSEQ, HD);

        // 4) scores[:,l,:] += Qf[l] @ pt[l]^T (batched over l=512) [128,512] K=64
        tgemm<128,128,64,32,true,0,true,false><<<dim3(4,1,LSEQ), 256, SMEM_NT_128x128>>>(
            Q, LSEQ*HD, (long long)HD,
            PT, HD, (long long)LSEQ*HD,
            S, LSEQ*LSEQ, (long long)LSEQ,
            nullptr, BHN, LSEQ, HD);

        // 5) softmax rows (rounded store)
        softmax512_kernel<<<BHN*LSEQ/8, dim3(32,8)>>>(S);

        // 6) AO = W @ V (batched over bh)  [512,64] K=512, NN
        tgemm<128,64,32,32,false,0,false,false><<<dim3(1,4,BHN), 256, SMEM_NN_128x64>>>(
            S, LSEQ, (long long)LSEQ*LSEQ, V, HD, (long long)LSEQ*HD,
            AO, HD, (long long)LSEQ*HD, nullptr, LSEQ, HD, LSEQ);

        // 7) AO[:,l,:] += W_l @ pt[l] (batched over l) [128,64] K=512, NN
        tgemm<128,64,32,32,false,0,true,false><<<dim3(1,1,LSEQ), 256, SMEM_NN_128x64>>>(
            S, LSEQ*LSEQ, (long long)LSEQ,
            PT, HD, (long long)LSEQ*HD,
            AO, LSEQ*HD, (long long)HD,
            nullptr, BHN, HD, LSEQ);

        // 8) reorder [bh,l,d] -> [l,b,e] (rounded)
        reorder_kernel<<<4096, 256>>>(AO, AL);

        // 9) Y = AL @ Wor^T + bo   [4096,1024] K=1024
        tgemm<128,128,64,32,true,1,false,false><<<dim3(8,32,1), 256, SMEM_NT_128x128>>>(
            AL, EE, 0, Wor + (size_t)l*EE*EE, EE, 0,
            Y, EE, 0, bo + (size_t)l*EE, MROWS, EE, EE);

        // 10) X1 = LN(x + Y)  (exact) + X1r (rounded)
        ln_res_kernel<<<MROWS, 256>>>(x, Y, g1 + (size_t)l*EE, be1 + (size_t)l*EE, X1, X1r);

        // 11) H = round(gelu(X1r @ W1r^T + b1))   [4096,4096] K=1024
        tgemm<128,128,64,32,true,2,false,true><<<dim3(32,32,1), 256, SMEM_NT_128x128>>>(
            X1r, EE, 0, W1r + (size_t)l*DFF*EE, EE, 0,
            Hb, DFF, 0, b1 + (size_t)l*DFF, MROWS, DFF, EE);

        // 12) Y = H @ W2r^T + b2   [4096,1024] K=4096
        tgemm<128,128,64,32,true,1,false,false><<<dim3(8,32,1), 256, SMEM_NT_128x128>>>(
            Hb, DFF, 0, W2r + (size_t)l*EE*DFF, DFF, 0,
            Y, EE, 0, b2 + (size_t)l*EE, MROWS, EE, DFF);

        // 13) next = LN(X1 + Y); last layer -> d_out (exact), else X + rounded Xr
        float* xo  = (l == NLAY-1) ? out : X;
        float* xor_ = (l == NLAY-1) ? nullptr : Xr;
        ln_res_kernel<<<MROWS, 256>>>(X1, Y, g2 + (size_t)l*EE, be2 + (size_t)l*EE, xo, xor_);

        x = X;
    }
}